// round 12
// baseline (speedup 1.0000x reference)
#include <cuda_runtime.h>

#define Ssz  1024
#define Hh   16
#define Dd   128
#define NBb  64
#define CBSs 32
#define KK   4
#define SBLK 32

#define NPICK   (Ssz * Hh * KK)        // 65536
#define NSRC    (NBb * Hh)             // 1024
#define CAPSRC  1024                   // max picks per src (<= #s)
#define SPLIT   4                      // fixed dest-split per src bucket

#define NEG_INF __int_as_float(0xff800000)

// scratch (no cudaMalloc allowed)
__device__ float g_ksum_t[Hh * Dd * NBb];     // [h][d][n]
__device__ int   g_cnt[NSRC];
__device__ int   g_lists[NSRC * CAPSRC];      // 4 MB

// ---------------------------------------------------------------------------
// K1: ksum[n,h,d] = sum_c kc[n,h,c,d] -> g_ksum_t[h][d][n], float4 loads.
// Also zeroes per-replay counters (grid == NSRC).
// ---------------------------------------------------------------------------
__global__ __launch_bounds__(128) void ksum_kernel(const float* __restrict__ kc) {
    const int b   = blockIdx.x;          // n*H + h
    const int tid = threadIdx.x;
    if (tid == 0) g_cnt[b] = 0;

    const int d4 = tid & 31, g = tid >> 5;
    const float4* base = (const float4*)(kc + (size_t)b * (CBSs * Dd));
    float4 acc = make_float4(0.f, 0.f, 0.f, 0.f);
#pragma unroll
    for (int c = 0; c < 8; ++c) {
        float4 v = base[(size_t)(g * 8 + c) * 32 + d4];
        acc.x += v.x; acc.y += v.y; acc.z += v.z; acc.w += v.w;
    }

    __shared__ float4 sh[128];
    sh[tid] = acc;
    __syncthreads();

    if (tid < 32) {
        float4 a = sh[tid], p = sh[tid + 32], q2 = sh[tid + 64], r = sh[tid + 96];
        a.x += p.x + q2.x + r.x;
        a.y += p.y + q2.y + r.y;
        a.z += p.z + q2.z + r.z;
        a.w += p.w + q2.w + r.w;
        const int n = b >> 4, h = b & (Hh - 1);
        const int d0 = tid * 4;
        g_ksum_t[(h * Dd + d0 + 0) * NBb + n] = a.x;
        g_ksum_t[(h * Dd + d0 + 1) * NBb + n] = a.y;
        g_ksum_t[(h * Dd + d0 + 2) * NBb + n] = a.z;
        g_ksum_t[(h * Dd + d0 + 3) * NBb + n] = a.w;
    }
}

// ---------------------------------------------------------------------------
// K2: block scores + top-4 (jax.lax.top_k: strict >, lowest index wins ties)
// with inline bucketing. Inner loop: 1 LDS.128 (4 consecutive n) + 2 scalar
// q broadcasts per 8 FFMA. Top-k: one warp per s-row, butterfly argmax.
// ---------------------------------------------------------------------------
__global__ __launch_bounds__(256) void score_topk_kernel(const float* __restrict__ q) {
    __shared__ float ksh[Dd * NBb];    // 32 KB, [d][n]
    __shared__ float qsh[SBLK * Dd];   // 16 KB (reused for scores [32][65])

    const int h  = blockIdx.y;
    const int s0 = blockIdx.x * SBLK;
    const int tid = threadIdx.x;

    // float4 staging
    {
        const float4* gk4 = (const float4*)(g_ksum_t + h * (Dd * NBb));
        float4* k4 = (float4*)ksh;
#pragma unroll
        for (int i = 0; i < 8; ++i)
            k4[tid + i * 256] = gk4[tid + i * 256];
        const float4* gq4 = (const float4*)q;
        float4* q4 = (float4*)qsh;
#pragma unroll
        for (int i = 0; i < 4; ++i) {
            int idx = tid + i * 256;                 // sl*32 + d4
            int sl = idx >> 5, d4 = idx & 31;
            q4[idx] = gq4[((size_t)(s0 + sl) * Hh + h) * 32 + d4];
        }
    }
    __syncthreads();

    const int ts = tid >> 4;        // s rows {ts, ts+16}
    const int tn = tid & 15;        // n cols {4tn..4tn+3}

    float acc[2][4];
#pragma unroll
    for (int i = 0; i < 2; ++i)
#pragma unroll
        for (int j = 0; j < 4; ++j) acc[i][j] = 0.f;

    const float4* k4 = (const float4*)ksh;
#pragma unroll 4
    for (int d = 0; d < Dd; ++d) {
        float4 kv = k4[d * 16 + tn];
        float q0 = qsh[ts * Dd + d];
        float q1 = qsh[(ts + 16) * Dd + d];
        acc[0][0] += q0 * kv.x; acc[0][1] += q0 * kv.y;
        acc[0][2] += q0 * kv.z; acc[0][3] += q0 * kv.w;
        acc[1][0] += q1 * kv.x; acc[1][1] += q1 * kv.y;
        acc[1][2] += q1 * kv.z; acc[1][3] += q1 * kv.w;
    }
    __syncthreads();

    float* sc = qsh;   // scores [SBLK][65] padded
#pragma unroll
    for (int i = 0; i < 2; ++i)
#pragma unroll
        for (int j = 0; j < 4; ++j)
            sc[(ts + 16 * i) * 65 + (tn * 4 + j)] = acc[i][j];
    __syncthreads();

    // top-4 per row: warp w handles rows w*4 .. w*4+3
    const int w = tid >> 5, l = tid & 31;
#pragma unroll
    for (int rr = 0; rr < 4; ++rr) {
        const int r = w * 4 + rr;
        float va = sc[r * 65 + l];
        float vb = sc[r * 65 + l + 32];
        const int outbase = ((s0 + r) * Hh + h) * KK;
#pragma unroll
        for (int p = 0; p < KK; ++p) {
            float v;  int idx;
            if (vb > va) { v = vb; idx = l + 32; }
            else         { v = va; idx = l; }
#pragma unroll
            for (int off = 16; off; off >>= 1) {
                float vo = __shfl_xor_sync(0xffffffffu, v, off);
                int   io = __shfl_xor_sync(0xffffffffu, idx, off);
                if (vo > v || (vo == v && io < idx)) { v = vo; idx = io; }
            }
            // all lanes agree on (v, idx); exclude and emit
            if (idx == l)      va = NEG_INF;
            if (idx == l + 32) vb = NEG_INF;
            if (l == 0) {
                int src = idx * Hh + h;
                int pos = atomicAdd(&g_cnt[src], 1);
                g_lists[src * CAPSRC + pos] = outbase + p;
            }
        }
    }
}

// ---------------------------------------------------------------------------
// K3: gather with fixed 4-way bucket split. CTA b: src = b>>2, slot = b&3.
// Load 16KB K + 16KB V src block into registers ONCE, replay with streaming
// stores.
// ---------------------------------------------------------------------------
__global__ __launch_bounds__(256) void gather_kernel(const float* __restrict__ kc,
                                                     const float* __restrict__ vc,
                                                     float* __restrict__ out) {
    const int b    = blockIdx.x;
    const int src  = b >> 2;
    const int slot = b & (SPLIT - 1);
    const int cnt  = g_cnt[src];
    if (slot >= cnt) return;

    const size_t blk4 = (size_t)(CBSs * Dd / 4);          // 1024 float4
    const float4* sk = (const float4*)kc + (size_t)src * blk4;
    const float4* sv = (const float4*)vc + (size_t)src * blk4;
    const int tid = threadIdx.x;

    float4 rk[4], rv[4];
#pragma unroll
    for (int i = 0; i < 4; ++i) {
        rk[i] = sk[tid + i * 256];
        rv[i] = sv[tid + i * 256];
    }

    const int* lst = g_lists + src * CAPSRC;
    for (int t = slot; t < cnt; t += SPLIT) {
        int dest = __ldg(lst + t);
        float4* dk = (float4*)out + (size_t)dest * blk4;
        float4* dv = dk + (size_t)NPICK * blk4;
#pragma unroll
        for (int i = 0; i < 4; ++i) {
            __stcs(dk + tid + i * 256, rk[i]);
            __stcs(dv + tid + i * 256, rv[i]);
        }
    }
}

extern "C" void kernel_launch(void* const* d_in, const int* in_sizes, int n_in,
                              void* d_out, int out_size) {
    const float* q  = (const float*)d_in[0];
    const float* kc = (const float*)d_in[1];
    const float* vc = (const float*)d_in[2];
    float* out = (float*)d_out;

    ksum_kernel<<<NSRC, 128>>>(kc);
    score_topk_kernel<<<dim3(Ssz / SBLK, Hh), 256>>>(q);
    gather_kernel<<<NSRC * SPLIT, 256>>>(kc, vc, out);
}

// round 13
// speedup vs baseline: 1.0081x; 1.0081x over previous
#include <cuda_runtime.h>

#define Ssz  1024
#define Hh   16
#define Dd   128
#define NBb  64
#define CBSs 32
#define KK   4
#define SBLK 32

#define NPICK   (Ssz * Hh * KK)        // 65536
#define NSRC    (NBb * Hh)             // 1024
#define CAPSRC  1024                   // max picks per src (<= #s)
#define SPLIT   4                      // fixed dest-split per src bucket

#define NEG_INF __int_as_float(0xff800000)

// scratch (no cudaMalloc allowed)
__device__ float g_ksum_t[Hh * Dd * NBb];     // [h][d][n]
__device__ int   g_cnt[NSRC];
__device__ int   g_lists[NSRC * CAPSRC];      // 4 MB

// ---------------------------------------------------------------------------
// K1: ksum[n,h,d] = sum_c kc[n,h,c,d] -> g_ksum_t[h][d][n], float4 loads.
// Also zeroes per-replay counters (grid == NSRC).
// ---------------------------------------------------------------------------
__global__ __launch_bounds__(128) void ksum_kernel(const float* __restrict__ kc) {
    const int b   = blockIdx.x;          // n*H + h
    const int tid = threadIdx.x;
    if (tid == 0) g_cnt[b] = 0;

    const int d4 = tid & 31, g = tid >> 5;
    const float4* base = (const float4*)(kc + (size_t)b * (CBSs * Dd));
    float4 acc = make_float4(0.f, 0.f, 0.f, 0.f);
#pragma unroll
    for (int c = 0; c < 8; ++c) {
        float4 v = base[(size_t)(g * 8 + c) * 32 + d4];
        acc.x += v.x; acc.y += v.y; acc.z += v.z; acc.w += v.w;
    }

    __shared__ float4 sh[128];
    sh[tid] = acc;
    __syncthreads();

    if (tid < 32) {
        float4 a = sh[tid], p = sh[tid + 32], q2 = sh[tid + 64], r = sh[tid + 96];
        a.x += p.x + q2.x + r.x;
        a.y += p.y + q2.y + r.y;
        a.z += p.z + q2.z + r.z;
        a.w += p.w + q2.w + r.w;
        const int n = b >> 4, h = b & (Hh - 1);
        const int d0 = tid * 4;
        g_ksum_t[(h * Dd + d0 + 0) * NBb + n] = a.x;
        g_ksum_t[(h * Dd + d0 + 1) * NBb + n] = a.y;
        g_ksum_t[(h * Dd + d0 + 2) * NBb + n] = a.z;
        g_ksum_t[(h * Dd + d0 + 3) * NBb + n] = a.w;
    }
}

// ---------------------------------------------------------------------------
// K2: block scores + top-4 (jax.lax.top_k: strict >, lowest index wins ties)
// with inline bucketing. Inner loop: 1 LDS.128 (4 consecutive n) + 2 scalar
// q broadcasts per 8 FFMA. Top-k: one warp per s-row, butterfly argmax.
// ---------------------------------------------------------------------------
__global__ __launch_bounds__(256) void score_topk_kernel(const float* __restrict__ q) {
    __shared__ float ksh[Dd * NBb];    // 32 KB, [d][n]
    __shared__ float qsh[SBLK * Dd];   // 16 KB (reused for scores [32][65])

    const int h  = blockIdx.y;
    const int s0 = blockIdx.x * SBLK;
    const int tid = threadIdx.x;

    // float4 staging
    {
        const float4* gk4 = (const float4*)(g_ksum_t + h * (Dd * NBb));
        float4* k4 = (float4*)ksh;
#pragma unroll
        for (int i = 0; i < 8; ++i)
            k4[tid + i * 256] = gk4[tid + i * 256];
        const float4* gq4 = (const float4*)q;
        float4* q4 = (float4*)qsh;
#pragma unroll
        for (int i = 0; i < 4; ++i) {
            int idx = tid + i * 256;                 // sl*32 + d4
            int sl = idx >> 5, d4 = idx & 31;
            q4[idx] = gq4[((size_t)(s0 + sl) * Hh + h) * 32 + d4];
        }
    }
    __syncthreads();

    const int ts = tid >> 4;        // s rows {ts, ts+16}
    const int tn = tid & 15;        // n cols {4tn..4tn+3}

    float acc[2][4];
#pragma unroll
    for (int i = 0; i < 2; ++i)
#pragma unroll
        for (int j = 0; j < 4; ++j) acc[i][j] = 0.f;

    const float4* k4 = (const float4*)ksh;
#pragma unroll 4
    for (int d = 0; d < Dd; ++d) {
        float4 kv = k4[d * 16 + tn];
        float q0 = qsh[ts * Dd + d];
        float q1 = qsh[(ts + 16) * Dd + d];
        acc[0][0] += q0 * kv.x; acc[0][1] += q0 * kv.y;
        acc[0][2] += q0 * kv.z; acc[0][3] += q0 * kv.w;
        acc[1][0] += q1 * kv.x; acc[1][1] += q1 * kv.y;
        acc[1][2] += q1 * kv.z; acc[1][3] += q1 * kv.w;
    }
    __syncthreads();

    float* sc = qsh;   // scores [SBLK][65] padded
#pragma unroll
    for (int i = 0; i < 2; ++i)
#pragma unroll
        for (int j = 0; j < 4; ++j)
            sc[(ts + 16 * i) * 65 + (tn * 4 + j)] = acc[i][j];
    __syncthreads();

    // top-4 per row: warp w handles rows w*4 .. w*4+3
    const int w = tid >> 5, l = tid & 31;
#pragma unroll
    for (int rr = 0; rr < 4; ++rr) {
        const int r = w * 4 + rr;
        float va = sc[r * 65 + l];
        float vb = sc[r * 65 + l + 32];
        const int outbase = ((s0 + r) * Hh + h) * KK;
#pragma unroll
        for (int p = 0; p < KK; ++p) {
            float v;  int idx;
            if (vb > va) { v = vb; idx = l + 32; }
            else         { v = va; idx = l; }
#pragma unroll
            for (int off = 16; off; off >>= 1) {
                float vo = __shfl_xor_sync(0xffffffffu, v, off);
                int   io = __shfl_xor_sync(0xffffffffu, idx, off);
                if (vo > v || (vo == v && io < idx)) { v = vo; idx = io; }
            }
            // all lanes agree on (v, idx); exclude and emit
            if (idx == l)      va = NEG_INF;
            if (idx == l + 32) vb = NEG_INF;
            if (l == 0) {
                int src = idx * Hh + h;
                int pos = atomicAdd(&g_cnt[src], 1);
                g_lists[src * CAPSRC + pos] = outbase + p;
            }
        }
    }
}

// ---------------------------------------------------------------------------
// K3: gather with fixed 4-way bucket split. CTA b: src = b>>2, slot = b&3.
// Load 16KB K + 16KB V src block into registers ONCE, replay with streaming
// stores.
// ---------------------------------------------------------------------------
__global__ __launch_bounds__(256) void gather_kernel(const float* __restrict__ kc,
                                                     const float* __restrict__ vc,
                                                     float* __restrict__ out) {
    const int b    = blockIdx.x;
    const int src  = b >> 2;
    const int slot = b & (SPLIT - 1);
    const int cnt  = g_cnt[src];
    if (slot >= cnt) return;

    const size_t blk4 = (size_t)(CBSs * Dd / 4);          // 1024 float4
    const float4* sk = (const float4*)kc + (size_t)src * blk4;
    const float4* sv = (const float4*)vc + (size_t)src * blk4;
    const int tid = threadIdx.x;

    float4 rk[4], rv[4];
#pragma unroll
    for (int i = 0; i < 4; ++i) {
        rk[i] = sk[tid + i * 256];
        rv[i] = sv[tid + i * 256];
    }

    const int* lst = g_lists + src * CAPSRC;
    for (int t = slot; t < cnt; t += SPLIT) {
        int dest = __ldg(lst + t);
        float4* dk = (float4*)out + (size_t)dest * blk4;
        float4* dv = dk + (size_t)NPICK * blk4;
#pragma unroll
        for (int i = 0; i < 4; ++i) {
            __stcs(dk + tid + i * 256, rk[i]);
            __stcs(dv + tid + i * 256, rv[i]);
        }
    }
}

extern "C" void kernel_launch(void* const* d_in, const int* in_sizes, int n_in,
                              void* d_out, int out_size) {
    const float* q  = (const float*)d_in[0];
    const float* kc = (const float*)d_in[1];
    const float* vc = (const float*)d_in[2];
    float* out = (float*)d_out;

    ksum_kernel<<<NSRC, 128>>>(kc);
    score_topk_kernel<<<dim3(Ssz / SBLK, Hh), 256>>>(q);
    gather_kernel<<<NSRC * SPLIT, 256>>>(kc, vc, out);
}